// round 15
// baseline (speedup 1.0000x reference)
#include <cuda_runtime.h>
#include <cuda_bf16.h>
#include <cstdint>

#define D1 270
#define KK 32
#define CC 60
#define BB 64
#define TT 4096
#define KL (KK*KK)        // 1024

// ---------------- scratch (no allocs allowed) ----------------
__device__ float g_cos[KL * CC];   // [kl][c]
__device__ float g_sin[KL * CC];
__device__ float g_wT[CC * D1];    // [c][j] transposed for coalesced fills

// ---------------- K0: alignment dummy (keeps ncu -s 5 -c 1 on k_mix) -------
__global__ void k_nop() {}

// ---------------- K1: sin/cos tables ----------------
__global__ void k_tables(const float* __restrict__ loc) {
    int idx = blockIdx.x * blockDim.x + threadIdx.x;
    if (idx >= KL * CC) return;
    int kl = idx / CC;
    int c  = idx - kl * CC;
    int k = kl >> 5, l = kl & 31;
    float t = (float)k * loc[2 * c] + (float)l * loc[2 * c + 1];
    float s, co;
    sincosf(6.283185307179586f * t, &s, &co);
    g_cos[idx] = co;
    g_sin[idx] = s;
}

// ---------------- K2: a[j,c] + softmax -> g_wT[c][j] -----------------------
__global__ __launch_bounds__(512) void k_weights(const float* __restrict__ z_re,
                                                 const float* __restrict__ z_im) {
    int j   = blockIdx.x;
    int tid = threadIdx.x;
    int c   = tid & 63;
    int s   = tid >> 6;             // 8 kl-slices

    float partial = 0.f;
    if (c < CC) {
        const float* zr = z_re + (size_t)j * KL;
        const float* zi = z_im + (size_t)j * KL;
        for (int kl = s; kl < KL; kl += 8) {
            partial += zr[kl] * g_cos[kl * CC + c] + zi[kl] * g_sin[kl * CC + c];
        }
    }
    __shared__ float sp[8][64];
    __shared__ float aval[64];
    __shared__ float red[2];
    sp[s][c] = partial;
    __syncthreads();
    if (tid < 64) {
        float v = 0.f;
#pragma unroll
        for (int i = 0; i < 8; i++) v += sp[i][tid];
        aval[tid] = v;
    }
    __syncthreads();
    if (tid == 0) {
        float m = -1e30f;
        for (int i = 0; i < CC; i++) m = fmaxf(m, aval[i]);
        float ssum = 0.f;
        for (int i = 0; i < CC; i++) ssum += expf(aval[i] - m);
        red[0] = m;
        red[1] = ssum;
    }
    __syncthreads();
    if (tid < CC) {
        g_wT[tid * D1 + j] = expf(aval[tid] - red[0]) / red[1];
    }
}

// ---------------- K3: HMMA GEMM out[b] = W @ X[b] (bf16 hi/lo, 3 passes) ---
// CTA 128j x 128t, 8 warps (4j x 2t), warp tile 32j x 64t.
// Smem: rows of 128 bf16 (hi k=0..63 | lo k=64..127), stride 136 bf16 = 272 B.
#define KSB   136                   // smem row stride in bf16 (272 B, 16B-mult)
#define ROWB  (KSB * 2)             // 272
#define WS_OFF 0
#define XS_OFF (128 * ROWB)         // 34816
#define SMEM3  (2 * 128 * ROWB)     // 69632

__device__ __forceinline__ void ldsm_x4(uint32_t* r, uint32_t addr) {
    asm volatile("ldmatrix.sync.aligned.m8n8.x4.shared.b16 {%0,%1,%2,%3}, [%4];"
                 : "=r"(r[0]), "=r"(r[1]), "=r"(r[2]), "=r"(r[3]) : "r"(addr));
}
__device__ __forceinline__ void ldsm_x2(uint32_t* r, uint32_t addr) {
    // NON-trans: [t][k] storage already matches the B fragment (pair spans k at fixed n)
    asm volatile("ldmatrix.sync.aligned.m8n8.x2.shared.b16 {%0,%1}, [%2];"
                 : "=r"(r[0]), "=r"(r[1]) : "r"(addr));
}
__device__ __forceinline__ void mma_bf16(float* d, const uint32_t* a, const uint32_t* b) {
    asm volatile("mma.sync.aligned.m16n8k16.row.col.f32.bf16.bf16.f32 "
                 "{%0,%1,%2,%3}, {%4,%5,%6,%7}, {%8,%9}, {%0,%1,%2,%3};"
                 : "+f"(d[0]), "+f"(d[1]), "+f"(d[2]), "+f"(d[3])
                 : "r"(a[0]), "r"(a[1]), "r"(a[2]), "r"(a[3]), "r"(b[0]), "r"(b[1]));
}
__device__ __forceinline__ uint32_t smem_u32(const void* p) {
    uint32_t a;
    asm("{ .reg .u64 t; cvta.to.shared.u64 t, %1; cvt.u32.u64 %0, t; }"
        : "=r"(a) : "l"(p));
    return a;
}
__device__ __forceinline__ uint32_t pack_bf16x2(float a, float b) {
    __nv_bfloat162 v = __floats2bfloat162_rn(a, b);   // low = a, high = b
    return *reinterpret_cast<uint32_t*>(&v);
}

__global__ __launch_bounds__(256) void k_mix(const float* __restrict__ X,
                                             float* __restrict__ out) {
    extern __shared__ char smem[];
    uint32_t sb = smem_u32(smem);
    int tid  = threadIdx.x;
    int wid  = tid >> 5;
    int lane = tid & 31;

    int jt = blockIdx.x % 3;
    int tt = blockIdx.x / 3;
    int b  = blockIdx.y;
    int j0 = jt * 128;
    int t0 = tt * 128;

    int jw = (wid & 3) * 32;        // warp j offset within tile
    int tw = (wid >> 2) * 64;       // warp t offset within tile

    // ---- fill Ws: W[j][c] hi/lo bf16, 8 c per thread, STS.128 ----
    for (int task = tid; task < 128 * 8; task += 256) {
        int jl = task & 127, cg = (task >> 7) * 8;
        int jj = j0 + jl; if (jj > D1 - 1) jj = D1 - 1;
        float v[8];
#pragma unroll
        for (int u = 0; u < 8; u++) {
            int c = cg + u;
            v[u] = (c < CC) ? g_wT[c * D1 + jj] : 0.f;
        }
        uint4 ph, pl;
        float lo[8];
        __nv_bfloat16 hb[8];
#pragma unroll
        for (int u = 0; u < 8; u++) { hb[u] = __float2bfloat16(v[u]); lo[u] = v[u] - __bfloat162float(hb[u]); }
        ph.x = pack_bf16x2(v[0], v[1]); ph.y = pack_bf16x2(v[2], v[3]);
        ph.z = pack_bf16x2(v[4], v[5]); ph.w = pack_bf16x2(v[6], v[7]);
        pl.x = pack_bf16x2(lo[0], lo[1]); pl.y = pack_bf16x2(lo[2], lo[3]);
        pl.z = pack_bf16x2(lo[4], lo[5]); pl.w = pack_bf16x2(lo[6], lo[7]);
        char* row = smem + WS_OFF + jl * ROWB;
        *(uint4*)(row + cg * 2)       = ph;    // hi at k = cg
        *(uint4*)(row + 128 + cg * 2) = pl;    // lo at k = 64 + cg
    }
    // ---- fill Xs: X[b][c][t0+t] -> [t][k] hi/lo ----
    const float* Xb = X + (size_t)b * CC * TT + t0;
    for (int task = tid; task < 128 * 8; task += 256) {
        int t = task & 127, cg = (task >> 7) * 8;
        float v[8];
#pragma unroll
        for (int u = 0; u < 8; u++) {
            int c = cg + u;
            v[u] = (c < CC) ? Xb[(size_t)c * TT + t] : 0.f;
        }
        uint4 ph, pl;
        float lo[8];
        __nv_bfloat16 hb[8];
#pragma unroll
        for (int u = 0; u < 8; u++) { hb[u] = __float2bfloat16(v[u]); lo[u] = v[u] - __bfloat162float(hb[u]); }
        ph.x = pack_bf16x2(v[0], v[1]); ph.y = pack_bf16x2(v[2], v[3]);
        ph.z = pack_bf16x2(v[4], v[5]); ph.w = pack_bf16x2(v[6], v[7]);
        pl.x = pack_bf16x2(lo[0], lo[1]); pl.y = pack_bf16x2(lo[2], lo[3]);
        pl.z = pack_bf16x2(lo[4], lo[5]); pl.w = pack_bf16x2(lo[6], lo[7]);
        char* row = smem + XS_OFF + t * ROWB;
        *(uint4*)(row + cg * 2)       = ph;
        *(uint4*)(row + 128 + cg * 2) = pl;
    }
    __syncthreads();

    // ---- ldmatrix base addresses ----
    // A x4: lanes 0-15 -> rows 0..15, lanes 16-31 -> same rows @ k+8 (+16B)
    uint32_t a_base0 = sb + WS_OFF + (uint32_t)(jw + (lane & 15)) * ROWB + ((lane >> 4) << 4);
    uint32_t a_base1 = a_base0 + 16 * ROWB;
    // B x2 non-trans: lanes 0-7 -> t rows @ k chunk, lanes 8-15 -> same rows @ k+8
    uint32_t b_base = sb + XS_OFF + (uint32_t)(tw + (lane & 7)) * ROWB + (((lane >> 3) & 1) << 4);

    float acc[2][8][4];
#pragma unroll
    for (int mi = 0; mi < 2; mi++)
#pragma unroll
        for (int ni = 0; ni < 8; ni++)
#pragma unroll
            for (int q = 0; q < 4; q++) acc[mi][ni][q] = 0.f;

    // ---- 12 K-steps: (hi,hi)x4, (hi,lo)x4, (lo,hi)x4 ----
#pragma unroll
    for (int ks = 0; ks < 12; ks++) {
        int pass = ks >> 2, pa = ks & 3;
        int ka2 = pa * 32 + (pass == 2 ? 128 : 0);   // byte offset in row
        int kb2 = pa * 32 + (pass == 1 ? 128 : 0);
        uint32_t a0[4], a1[4];
        ldsm_x4(a0, a_base0 + ka2);
        ldsm_x4(a1, a_base1 + ka2);
#pragma unroll
        for (int ni = 0; ni < 8; ni++) {
            uint32_t bb[2];
            ldsm_x2(bb, b_base + ni * 8 * ROWB + kb2);
            mma_bf16(acc[0][ni], a0, bb);
            mma_bf16(acc[1][ni], a1, bb);
        }
    }

    // ---- epilogue: direct float2 stores from fragments ----
    float* outp = out + (size_t)b * D1 * TT + t0 + tw;
#pragma unroll
    for (int mi = 0; mi < 2; mi++) {
#pragma unroll
        for (int ni = 0; ni < 8; ni++) {
            int col = ni * 8 + (lane & 3) * 2;
            int jr  = j0 + jw + mi * 16 + (lane >> 2);
            if (jr < D1)
                __stcs((float2*)&outp[(size_t)jr * TT + col],
                       make_float2(acc[mi][ni][0], acc[mi][ni][1]));
            if (jr + 8 < D1)
                __stcs((float2*)&outp[(size_t)(jr + 8) * TT + col],
                       make_float2(acc[mi][ni][2], acc[mi][ni][3]));
        }
    }
}

// ---------------- launch ----------------
extern "C" void kernel_launch(void* const* d_in, const int* in_sizes, int n_in,
                              void* d_out, int out_size) {
    const float* X    = (const float*)d_in[0];
    const float* z_re = (const float*)d_in[1];
    const float* z_im = (const float*)d_in[2];
    const float* loc  = (const float*)d_in[3];
    float* out = (float*)d_out;

    k_nop<<<1, 32>>>();
    k_tables<<<(KL * CC + 255) / 256, 256>>>(loc);
    k_weights<<<D1, 512>>>(z_re, z_im);

    cudaFuncSetAttribute(k_mix, cudaFuncAttributeMaxDynamicSharedMemorySize, SMEM3);
    cudaFuncSetAttribute(k_mix, cudaFuncAttributePreferredSharedMemoryCarveout,
                         cudaSharedmemCarveoutMaxShared);
    k_mix<<<dim3(3 * (TT / 128), BB), 256, SMEM3>>>(X, out);
}

// round 16
// speedup vs baseline: 1.4785x; 1.4785x over previous
#include <cuda_runtime.h>
#include <cuda_bf16.h>
#include <cstdint>

#define D1 270
#define KK 32
#define CC 60
#define BB 64
#define TT 4096
#define KL (KK*KK)        // 1024

// ---------------- scratch (no allocs allowed) ----------------
__device__ float g_cos[KL * CC];   // [kl][c]
__device__ float g_sin[KL * CC];
__device__ float g_wT[CC * D1];    // [c][j] transposed for coalesced fills

// ---------------- K0: alignment dummy (keeps ncu -s 5 -c 1 on k_mix) -------
__global__ void k_nop() {}

// ---------------- K1: sin/cos tables ----------------
__global__ void k_tables(const float* __restrict__ loc) {
    int idx = blockIdx.x * blockDim.x + threadIdx.x;
    if (idx >= KL * CC) return;
    int kl = idx / CC;
    int c  = idx - kl * CC;
    int k = kl >> 5, l = kl & 31;
    float t = (float)k * loc[2 * c] + (float)l * loc[2 * c + 1];
    float s, co;
    sincosf(6.283185307179586f * t, &s, &co);
    g_cos[idx] = co;
    g_sin[idx] = s;
}

// ---------------- K2: a[j,c] + softmax -> g_wT[c][j] -----------------------
__global__ __launch_bounds__(512) void k_weights(const float* __restrict__ z_re,
                                                 const float* __restrict__ z_im) {
    int j   = blockIdx.x;
    int tid = threadIdx.x;
    int c   = tid & 63;
    int s   = tid >> 6;             // 8 kl-slices

    float partial = 0.f;
    if (c < CC) {
        const float* zr = z_re + (size_t)j * KL;
        const float* zi = z_im + (size_t)j * KL;
        for (int kl = s; kl < KL; kl += 8) {
            partial += zr[kl] * g_cos[kl * CC + c] + zi[kl] * g_sin[kl * CC + c];
        }
    }
    __shared__ float sp[8][64];
    __shared__ float aval[64];
    __shared__ float red[2];
    sp[s][c] = partial;
    __syncthreads();
    if (tid < 64) {
        float v = 0.f;
#pragma unroll
        for (int i = 0; i < 8; i++) v += sp[i][tid];
        aval[tid] = v;
    }
    __syncthreads();
    if (tid == 0) {
        float m = -1e30f;
        for (int i = 0; i < CC; i++) m = fmaxf(m, aval[i]);
        float ssum = 0.f;
        for (int i = 0; i < CC; i++) ssum += expf(aval[i] - m);
        red[0] = m;
        red[1] = ssum;
    }
    __syncthreads();
    if (tid < CC) {
        g_wT[tid * D1 + j] = expf(aval[tid] - red[0]) / red[1];
    }
}

// ---------------- K3: HMMA GEMM out[b] = W @ X[b] (bf16 hi/lo, 3 passes) ---
// CTA 96j x 128t, 192 thr = 6 warps (3j x 2t), warp tile 32j x 64t.
// Smem rows: 128 bf16 (hi k=0..63 | lo k=64..127), stride 272 B.
#define ROWB  272
#define NJ    96                    // CTA j-rows
#define WS_OFF 0
#define XS_OFF (NJ * ROWB)          // 26112
#define SMEM3  (XS_OFF + 128 * ROWB)  // 60928

__device__ __forceinline__ void ldsm_x4(uint32_t* r, uint32_t addr) {
    asm volatile("ldmatrix.sync.aligned.m8n8.x4.shared.b16 {%0,%1,%2,%3}, [%4];"
                 : "=r"(r[0]), "=r"(r[1]), "=r"(r[2]), "=r"(r[3]) : "r"(addr));
}
__device__ __forceinline__ void ldsm_x2(uint32_t* r, uint32_t addr) {
    asm volatile("ldmatrix.sync.aligned.m8n8.x2.shared.b16 {%0,%1}, [%2];"
                 : "=r"(r[0]), "=r"(r[1]) : "r"(addr));
}
__device__ __forceinline__ void mma_bf16(float* d, const uint32_t* a, const uint32_t* b) {
    asm volatile("mma.sync.aligned.m16n8k16.row.col.f32.bf16.bf16.f32 "
                 "{%0,%1,%2,%3}, {%4,%5,%6,%7}, {%8,%9}, {%0,%1,%2,%3};"
                 : "+f"(d[0]), "+f"(d[1]), "+f"(d[2]), "+f"(d[3])
                 : "r"(a[0]), "r"(a[1]), "r"(a[2]), "r"(a[3]), "r"(b[0]), "r"(b[1]));
}
__device__ __forceinline__ uint32_t smem_u32(const void* p) {
    uint32_t a;
    asm("{ .reg .u64 t; cvta.to.shared.u64 t, %1; cvt.u32.u64 %0, t; }"
        : "=r"(a) : "l"(p));
    return a;
}
__device__ __forceinline__ uint32_t pack_bf16x2(float a, float b) {
    __nv_bfloat162 v = __floats2bfloat162_rn(a, b);
    return *reinterpret_cast<uint32_t*>(&v);
}

__global__ __launch_bounds__(192, 2) void k_mix(const float* __restrict__ X,
                                                float* __restrict__ out) {
    extern __shared__ char smem[];
    uint32_t sb = smem_u32(smem);
    int tid  = threadIdx.x;
    int wid  = tid >> 5;            // 0..5
    int lane = tid & 31;

    int jt = blockIdx.x % 3;
    int tt = blockIdx.x / 3;
    int b  = blockIdx.y;
    int j0 = jt * NJ;
    int t0 = tt * 128;

    int jw = (wid >> 1) * 32;       // 0/32/64
    int tw = (wid & 1) * 64;        // 0/64

    // ---- fill Ws: W[j0+jl][c] hi/lo bf16, 8 c per thread, STS.128 ----
    for (int task = tid; task < NJ * 8; task += 192) {
        int jl = task % NJ, cg = (task / NJ) * 8;
        int jj = j0 + jl; if (jj > D1 - 1) jj = D1 - 1;
        float v[8], lo[8];
#pragma unroll
        for (int u = 0; u < 8; u++) {
            int c = cg + u;
            v[u] = (c < CC) ? g_wT[c * D1 + jj] : 0.f;
            lo[u] = v[u] - __bfloat162float(__float2bfloat16(v[u]));
        }
        uint4 ph, pl;
        ph.x = pack_bf16x2(v[0], v[1]); ph.y = pack_bf16x2(v[2], v[3]);
        ph.z = pack_bf16x2(v[4], v[5]); ph.w = pack_bf16x2(v[6], v[7]);
        pl.x = pack_bf16x2(lo[0], lo[1]); pl.y = pack_bf16x2(lo[2], lo[3]);
        pl.z = pack_bf16x2(lo[4], lo[5]); pl.w = pack_bf16x2(lo[6], lo[7]);
        char* row = smem + WS_OFF + jl * ROWB;
        *(uint4*)(row + cg * 2)       = ph;
        *(uint4*)(row + 128 + cg * 2) = pl;
    }
    // ---- fill Xs: X[b][c][t0+t] -> [t][k] hi/lo ----
    const float* Xb = X + (size_t)b * CC * TT + t0;
    for (int task = tid; task < 128 * 8; task += 192) {
        int t = task & 127, cg = (task >> 7) * 8;
        float v[8], lo[8];
#pragma unroll
        for (int u = 0; u < 8; u++) {
            int c = cg + u;
            v[u] = (c < CC) ? Xb[(size_t)c * TT + t] : 0.f;
            lo[u] = v[u] - __bfloat162float(__float2bfloat16(v[u]));
        }
        uint4 ph, pl;
        ph.x = pack_bf16x2(v[0], v[1]); ph.y = pack_bf16x2(v[2], v[3]);
        ph.z = pack_bf16x2(v[4], v[5]); ph.w = pack_bf16x2(v[6], v[7]);
        pl.x = pack_bf16x2(lo[0], lo[1]); pl.y = pack_bf16x2(lo[2], lo[3]);
        pl.z = pack_bf16x2(lo[4], lo[5]); pl.w = pack_bf16x2(lo[6], lo[7]);
        char* row = smem + XS_OFF + t * ROWB;
        *(uint4*)(row + cg * 2)       = ph;
        *(uint4*)(row + 128 + cg * 2) = pl;
    }
    __syncthreads();

    // ---- ldmatrix bases (verified fragment layout) ----
    uint32_t a_base0 = sb + WS_OFF + (uint32_t)(jw + (lane & 15)) * ROWB + ((lane >> 4) << 4);
    uint32_t a_base1 = a_base0 + 16 * ROWB;
    uint32_t b_base  = sb + XS_OFF + (uint32_t)(tw + (lane & 7)) * ROWB + (((lane >> 3) & 1) << 4);

    float acc[2][8][4];
#pragma unroll
    for (int mi = 0; mi < 2; mi++)
#pragma unroll
        for (int ni = 0; ni < 8; ni++)
#pragma unroll
            for (int q = 0; q < 4; q++) acc[mi][ni][q] = 0.f;

    // ---- 12 K-steps: (hi,hi)x4, (hi,lo)x4, (lo,hi)x4 ----
#pragma unroll
    for (int ks = 0; ks < 12; ks++) {
        int pass = ks >> 2, pa = ks & 3;
        int ka2 = pa * 32 + (pass == 2 ? 128 : 0);
        int kb2 = pa * 32 + (pass == 1 ? 128 : 0);
        uint32_t a0[4], a1[4];
        ldsm_x4(a0, a_base0 + ka2);
        ldsm_x4(a1, a_base1 + ka2);
        uint32_t bb[8][2];
#pragma unroll
        for (int ni = 0; ni < 8; ni++)
            ldsm_x2(bb[ni], b_base + ni * 8 * ROWB + kb2);
#pragma unroll
        for (int ni = 0; ni < 8; ni++) {
            mma_bf16(acc[0][ni], a0, bb[ni]);
            mma_bf16(acc[1][ni], a1, bb[ni]);
        }
    }

    // ---- epilogue: direct float2 stores ----
    float* outp = out + (size_t)b * D1 * TT + t0 + tw;
#pragma unroll
    for (int mi = 0; mi < 2; mi++) {
#pragma unroll
        for (int ni = 0; ni < 8; ni++) {
            int col = ni * 8 + (lane & 3) * 2;
            int jr  = j0 + jw + mi * 16 + (lane >> 2);
            if (jr < D1)
                __stcs((float2*)&outp[(size_t)jr * TT + col],
                       make_float2(acc[mi][ni][0], acc[mi][ni][1]));
            if (jr + 8 < D1)
                __stcs((float2*)&outp[(size_t)(jr + 8) * TT + col],
                       make_float2(acc[mi][ni][2], acc[mi][ni][3]));
        }
    }
}

// ---------------- launch ----------------
extern "C" void kernel_launch(void* const* d_in, const int* in_sizes, int n_in,
                              void* d_out, int out_size) {
    const float* X    = (const float*)d_in[0];
    const float* z_re = (const float*)d_in[1];
    const float* z_im = (const float*)d_in[2];
    const float* loc  = (const float*)d_in[3];
    float* out = (float*)d_out;

    k_nop<<<1, 32>>>();
    k_tables<<<(KL * CC + 255) / 256, 256>>>(loc);
    k_weights<<<D1, 512>>>(z_re, z_im);

    cudaFuncSetAttribute(k_mix, cudaFuncAttributeMaxDynamicSharedMemorySize, SMEM3);
    cudaFuncSetAttribute(k_mix, cudaFuncAttributePreferredSharedMemoryCarveout,
                         cudaSharedmemCarveoutMaxShared);
    k_mix<<<dim3(3 * (TT / 128), BB), 192, SMEM3>>>(X, out);
}